// round 1
// baseline (speedup 1.0000x reference)
#include <cuda_runtime.h>

// ---------------- problem constants ----------------
#define B_LON 30
#define NW    32
#define NTOK  144
#define CDIM  192
#define NH    6
#define HD    32
#define NBW   (B_LON * NW)          // 960
#define SCALE 0.17677669529663687f  // 1/sqrt(32)

// ---------------- scratch (device globals; no allocs allowed) ----------------
__device__ float g_q[NBW * NH * NTOK * HD];     // 106 MB, pre-scaled q, [bw][h][n][d]
__device__ float g_k[NBW * NH * NTOK * HD];
__device__ float g_v[NBW * NH * NTOK * HD];
__device__ float g_o[NBW * NTOK * CDIM];        // attention output, [bw][n][c]
__device__ float g_bias[CDIM * NTOK * NTOK];    // dense bias, [(w*6+h)][n][m] (15.9 MB)

// ---------------- kernel 0: densify earth-position bias ----------------
// bias_table: (3312, 32, 6) ; pos: (144,144) int32
// g_bias[(w*6+h)*20736 + n*144 + m] = bias_table[pos[n][m]*192 + w*6 + h]
__global__ __launch_bounds__(256) void bias_pre_kernel(
    const float* __restrict__ table, const int* __restrict__ pos) {
    __shared__ float sm[CDIM * 33];
    __shared__ int sidx[32];
    int p0 = blockIdx.x * 32;          // 32 (n,m) pairs per block; 648 blocks
    int tid = threadIdx.x;
    if (tid < 32) sidx[tid] = pos[p0 + tid];
    __syncthreads();
    // gather: coalesced 192-float rows of the table
    for (int i = tid; i < 32 * CDIM; i += 256) {
        int p = i / CDIM, whc = i % CDIM;
        sm[whc * 33 + p] = table[(long)sidx[p] * CDIM + whc];
    }
    __syncthreads();
    // scatter: coalesced 32-float runs per (w,h)
    for (int i = tid; i < 32 * CDIM; i += 256) {
        int wh = i / 32, p = i % 32;
        g_bias[(long)wh * (NTOK * NTOK) + p0 + p] = sm[wh * 33 + p];
    }
}

// ---------------- kernel 1: QKV projection ----------------
// per block: one (b,w) tile, x(144x192) @ qkv_w^T(192x576) + b
// writes q (scaled), k, v into head-major scratch
#define XS 196   // padded smem row stride
__global__ __launch_bounds__(256, 1) void qkv_kernel(
    const float* __restrict__ x, const float* __restrict__ wt,
    const float* __restrict__ bias) {
    extern __shared__ float sm[];
    float* sx = sm;                 // 144 x XS
    float* sw = sm + NTOK * XS;     // 64 x XS
    int bw = blockIdx.x;
    int tid = threadIdx.x;
    const float* xp = x + (long)bw * NTOK * CDIM;
    for (int i = tid; i < NTOK * CDIM / 4; i += 256) {
        int e = i * 4;
        int n = e / CDIM, k = e % CDIM;
        *(float4*)(sx + n * XS + k) = *(const float4*)(xp + e);
    }
    int ty = tid >> 4, tx = tid & 15;
    for (int ct = 0; ct < 9; ++ct) {               // 9 tiles of 64 output channels
        __syncthreads();
        int c0 = ct * 64;
        for (int i = tid; i < 64 * CDIM / 4; i += 256) {
            int e = i * 4;
            int j = e / CDIM, k = e % CDIM;
            *(float4*)(sw + j * XS + k) = *(const float4*)(wt + (long)(c0 + j) * CDIM + k);
        }
        __syncthreads();
        float acc[9][4];
#pragma unroll
        for (int i = 0; i < 9; i++)
#pragma unroll
            for (int j = 0; j < 4; j++) acc[i][j] = 0.f;
#pragma unroll 4
        for (int k = 0; k < CDIM; ++k) {
            float xr[9], wr[4];
#pragma unroll
            for (int i = 0; i < 9; i++) xr[i] = sx[(ty * 9 + i) * XS + k];
#pragma unroll
            for (int j = 0; j < 4; j++) wr[j] = sw[(tx + j * 16) * XS + k];
#pragma unroll
            for (int i = 0; i < 9; i++)
#pragma unroll
                for (int j = 0; j < 4; j++) acc[i][j] = fmaf(xr[i], wr[j], acc[i][j]);
        }
#pragma unroll
        for (int j = 0; j < 4; j++) {
            int c = c0 + tx + j * 16;
            int s = c / CDIM, rem = c % CDIM;
            int h = rem / HD, d = rem % HD;
            float bb = bias[c];
            float mul = (s == 0) ? SCALE : 1.f;
            float* dst = (s == 0) ? g_q : (s == 1) ? g_k : g_v;
            float* base = dst + (long)(bw * NH + h) * NTOK * HD + d;
#pragma unroll
            for (int i = 0; i < 9; i++) {
                int n = ty * 9 + i;
                base[n * HD] = (acc[i][j] + bb) * mul;
            }
        }
    }
}

// ---------------- kernel 2: fused attention per (b,w,h) ----------------
__global__ __launch_bounds__(256, 1) void attn_kernel(const float* __restrict__ mask) {
    extern __shared__ float sm[];
    float* sq = sm;                    // 144 x 33
    float* sk = sq + NTOK * 33;
    float* sv = sk + NTOK * 33;
    float* sa = sv + NTOK * 33;        // 144 x 145
    int h  = blockIdx.x;
    int bw = blockIdx.y;
    int w  = bw % NW;
    int tid = threadIdx.x;
    long base = (long)(bw * NH + h) * NTOK * HD;
    const float* qp = g_q + base;
    const float* kp = g_k + base;
    const float* vp = g_v + base;
    for (int i = tid; i < NTOK * HD; i += 256) {
        int n = i >> 5, d = i & 31;
        sq[n * 33 + d] = qp[i];
        sk[n * 33 + d] = kp[i];
        sv[n * 33 + d] = vp[i];
    }
    __syncthreads();
    int ty = tid >> 4, tx = tid & 15;
    // scores: (144x32) @ (144x32)^T  -> 9x9 micro-tile per thread
    float acc[9][9];
#pragma unroll
    for (int i = 0; i < 9; i++)
#pragma unroll
        for (int j = 0; j < 9; j++) acc[i][j] = 0.f;
#pragma unroll
    for (int d = 0; d < HD; ++d) {
        float qr[9], kr[9];
#pragma unroll
        for (int i = 0; i < 9; i++) qr[i] = sq[(ty * 9 + i) * 33 + d];
#pragma unroll
        for (int j = 0; j < 9; j++) kr[j] = sk[(tx + j * 16) * 33 + d];
#pragma unroll
        for (int i = 0; i < 9; i++)
#pragma unroll
            for (int j = 0; j < 9; j++) acc[i][j] = fmaf(qr[i], kr[j], acc[i][j]);
    }
    const float* bp = g_bias + (long)(w * NH + h) * NTOK * NTOK;
    const float* mp = mask + (long)bw * NTOK * NTOK;
#pragma unroll
    for (int i = 0; i < 9; i++) {
        int n = ty * 9 + i;
#pragma unroll
        for (int j = 0; j < 9; j++) {
            int m = tx + j * 16;
            sa[n * 145 + m] = acc[i][j] + bp[n * NTOK + m] + mp[n * NTOK + m];
        }
    }
    __syncthreads();
    // softmax: one warp per row-group
    int wid = tid >> 5, lane = tid & 31;
    for (int r = wid; r < NTOK; r += 8) {
        float mx = -1e30f;
        for (int c = lane; c < NTOK; c += 32) mx = fmaxf(mx, sa[r * 145 + c]);
#pragma unroll
        for (int o = 16; o; o >>= 1) mx = fmaxf(mx, __shfl_xor_sync(0xffffffffu, mx, o));
        float s = 0.f;
        for (int c = lane; c < NTOK; c += 32) {
            float e = __expf(sa[r * 145 + c] - mx);
            sa[r * 145 + c] = e;
            s += e;
        }
#pragma unroll
        for (int o = 16; o; o >>= 1) s += __shfl_xor_sync(0xffffffffu, s, o);
        float inv = 1.f / s;
        for (int c = lane; c < NTOK; c += 32) sa[r * 145 + c] *= inv;
    }
    __syncthreads();
    // PV: (144x144) @ (144x32) -> 9x2 micro-tile per thread
    float acc2[9][2];
#pragma unroll
    for (int i = 0; i < 9; i++) { acc2[i][0] = 0.f; acc2[i][1] = 0.f; }
#pragma unroll 4
    for (int m = 0; m < NTOK; ++m) {
        float ar[9], vr[2];
#pragma unroll
        for (int i = 0; i < 9; i++) ar[i] = sa[(ty * 9 + i) * 145 + m];
#pragma unroll
        for (int j = 0; j < 2; j++) vr[j] = sv[m * 33 + tx + j * 16];
#pragma unroll
        for (int i = 0; i < 9; i++)
#pragma unroll
            for (int j = 0; j < 2; j++) acc2[i][j] = fmaf(ar[i], vr[j], acc2[i][j]);
    }
    float* op = g_o + (long)bw * NTOK * CDIM;
#pragma unroll
    for (int i = 0; i < 9; i++) {
        int n = ty * 9 + i;
#pragma unroll
        for (int j = 0; j < 2; j++) {
            int d = tx + j * 16;
            op[n * CDIM + h * HD + d] = acc2[i][j];
        }
    }
}

// ---------------- kernel 3: output projection ----------------
__global__ __launch_bounds__(256, 1) void proj_kernel(
    const float* __restrict__ wt, const float* __restrict__ bias,
    float* __restrict__ out) {
    extern __shared__ float sm[];
    float* sx = sm;                 // 144 x XS
    float* sw = sm + NTOK * XS;     // 64 x XS
    int bw = blockIdx.x;
    int tid = threadIdx.x;
    const float* xp = g_o + (long)bw * NTOK * CDIM;
    for (int i = tid; i < NTOK * CDIM / 4; i += 256) {
        int e = i * 4;
        int n = e / CDIM, k = e % CDIM;
        *(float4*)(sx + n * XS + k) = *(const float4*)(xp + e);
    }
    int ty = tid >> 4, tx = tid & 15;
    for (int ct = 0; ct < 3; ++ct) {
        __syncthreads();
        int c0 = ct * 64;
        for (int i = tid; i < 64 * CDIM / 4; i += 256) {
            int e = i * 4;
            int j = e / CDIM, k = e % CDIM;
            *(float4*)(sw + j * XS + k) = *(const float4*)(wt + (long)(c0 + j) * CDIM + k);
        }
        __syncthreads();
        float acc[9][4];
#pragma unroll
        for (int i = 0; i < 9; i++)
#pragma unroll
            for (int j = 0; j < 4; j++) acc[i][j] = 0.f;
#pragma unroll 4
        for (int k = 0; k < CDIM; ++k) {
            float xr[9], wr[4];
#pragma unroll
            for (int i = 0; i < 9; i++) xr[i] = sx[(ty * 9 + i) * XS + k];
#pragma unroll
            for (int j = 0; j < 4; j++) wr[j] = sw[(tx + j * 16) * XS + k];
#pragma unroll
            for (int i = 0; i < 9; i++)
#pragma unroll
                for (int j = 0; j < 4; j++) acc[i][j] = fmaf(xr[i], wr[j], acc[i][j]);
        }
#pragma unroll
        for (int j = 0; j < 4; j++) {
            int c = c0 + tx + j * 16;
            float bb = bias[c];
#pragma unroll
            for (int i = 0; i < 9; i++) {
                int n = ty * 9 + i;
                out[(long)bw * NTOK * CDIM + n * CDIM + c] = acc[i][j] + bb;
            }
        }
    }
}

// ---------------- launch ----------------
extern "C" void kernel_launch(void* const* d_in, const int* in_sizes, int n_in,
                              void* d_out, int out_size) {
    const float* x      = (const float*)d_in[0];
    const float* mask   = (const float*)d_in[1];
    const float* qkv_w  = (const float*)d_in[2];
    const float* qkv_b  = (const float*)d_in[3];
    const float* proj_w = (const float*)d_in[4];
    const float* proj_b = (const float*)d_in[5];
    const float* table  = (const float*)d_in[6];
    const int*   pos    = (const int*)d_in[7];
    float* out = (float*)d_out;

    const int lin_smem  = (NTOK * XS + 64 * XS) * 4;      // 163072 B
    const int attn_smem = (3 * NTOK * 33 + NTOK * 145) * 4; // 140544 B
    cudaFuncSetAttribute(qkv_kernel,  cudaFuncAttributeMaxDynamicSharedMemorySize, lin_smem);
    cudaFuncSetAttribute(proj_kernel, cudaFuncAttributeMaxDynamicSharedMemorySize, lin_smem);
    cudaFuncSetAttribute(attn_kernel, cudaFuncAttributeMaxDynamicSharedMemorySize, attn_smem);

    bias_pre_kernel<<<(NTOK * NTOK) / 32, 256>>>(table, pos);
    qkv_kernel<<<NBW, 256, lin_smem>>>(x, qkv_w, qkv_b);
    attn_kernel<<<dim3(NH, NBW), 256, attn_smem>>>(mask);
    proj_kernel<<<NBW, 256, lin_smem>>>(proj_w, proj_b, out);
}

// round 3
// speedup vs baseline: 1.6156x; 1.6156x over previous
#include <cuda_runtime.h>
#include <cstdint>

// ---------------- problem constants ----------------
#define B_LON 30
#define NW    32
#define NTOK  144
#define CDIM  192
#define NH    6
#define HD    32
#define NBW   (B_LON * NW)          // 960
#define SCALE 0.17677669529663687f  // 1/sqrt(32)

#define SXS 196   // x / weight smem row stride (floats)
#define QVS 40    // q/k/v smem row stride
#define SAS 148   // score smem row stride

// ---------------- scratch (device globals; no allocs allowed) ----------------
__device__ float g_q[NBW * NH * NTOK * HD];     // pre-scaled, tf32-rounded, [bw][h][n][d]
__device__ float g_k[NBW * NH * NTOK * HD];
__device__ float g_v[NBW * NH * NTOK * HD];
__device__ float g_o[NBW * NTOK * CDIM];        // attention output, [bw][n][c]
__device__ float g_bias[CDIM * NTOK * NTOK];    // dense bias, [(w*6+h)][n][m]

// ---------------- helpers ----------------
__device__ __forceinline__ uint32_t f2tf(float x) {
    uint32_t r; asm("cvt.rna.tf32.f32 %0, %1;" : "=r"(r) : "f"(x)); return r;
}
__device__ __forceinline__ float f2tff(float x) {
    return __uint_as_float(f2tf(x));
}
__device__ __forceinline__ void mma_tf32(float c[4], uint32_t a0, uint32_t a1,
                                         uint32_t a2, uint32_t a3,
                                         uint32_t b0, uint32_t b1) {
    asm volatile(
        "mma.sync.aligned.m16n8k8.row.col.f32.tf32.tf32.f32 "
        "{%0,%1,%2,%3}, {%4,%5,%6,%7}, {%8,%9}, {%0,%1,%2,%3};\n"
        : "+f"(c[0]), "+f"(c[1]), "+f"(c[2]), "+f"(c[3])
        : "r"(a0), "r"(a1), "r"(a2), "r"(a3), "r"(b0), "r"(b1));
}

// ---------------- kernel 0: densify earth-position bias ----------------
__global__ __launch_bounds__(256) void bias_pre_kernel(
    const float* __restrict__ table, const int* __restrict__ pos) {
    __shared__ float sm[CDIM * 33];
    __shared__ int sidx[32];
    int p0 = blockIdx.x * 32;
    int tid = threadIdx.x;
    if (tid < 32) sidx[tid] = pos[p0 + tid];
    __syncthreads();
    for (int i = tid; i < 32 * CDIM; i += 256) {
        int p = i / CDIM, whc = i % CDIM;
        sm[whc * 33 + p] = table[(long)sidx[p] * CDIM + whc];
    }
    __syncthreads();
    for (int i = tid; i < 32 * CDIM; i += 256) {
        int wh = i / 32, p = i % 32;
        g_bias[(long)wh * (NTOK * NTOK) + p0 + p] = sm[wh * 33 + p];
    }
}

// ---------------- kernel 1: QKV projection (tf32 MMA) ----------------
// per block (bw): x(144x192) @ qkv_w^T(192x576) + b ; 288 threads = 9 warps,
// warp w owns M-rows [16w, 16w+16). N processed in 9 chunks of 64.
__global__ __launch_bounds__(288, 1) void qkv_kernel(
    const float* __restrict__ x, const float* __restrict__ wt,
    const float* __restrict__ bias) {
    extern __shared__ float sm[];
    float* sx = sm;                 // 144 x SXS (tf32-rounded)
    float* sw = sm + NTOK * SXS;    // 64 x SXS
    int bw = blockIdx.x;
    int tid = threadIdx.x;
    int warp = tid >> 5, lane = tid & 31, gp = lane >> 2, tg = lane & 3;
    int m0 = warp * 16;

    const float* xp = x + (long)bw * NTOK * CDIM;
    for (int i = tid; i < NTOK * CDIM / 4; i += 288) {
        int e = i * 4;
        int n = e / CDIM, k = e % CDIM;
        float4 v = *(const float4*)(xp + e);
        float* d = sx + n * SXS + k;
        d[0] = f2tff(v.x); d[1] = f2tff(v.y); d[2] = f2tff(v.z); d[3] = f2tff(v.w);
    }

    for (int ct = 0; ct < 9; ++ct) {
        __syncthreads();
        int c0 = ct * 64;
        for (int i = tid; i < 64 * CDIM / 4; i += 288) {
            int e = i * 4;
            int j = e / CDIM, k = e % CDIM;
            float4 v = *(const float4*)(wt + (long)(c0 + j) * CDIM + k);
            float* d = sw + j * SXS + k;
            d[0] = f2tff(v.x); d[1] = f2tff(v.y); d[2] = f2tff(v.z); d[3] = f2tff(v.w);
        }
        __syncthreads();
        float acc[8][4];
#pragma unroll
        for (int t = 0; t < 8; t++)
#pragma unroll
            for (int j = 0; j < 4; j++) acc[t][j] = 0.f;
#pragma unroll
        for (int kk = 0; kk < 24; ++kk) {
            int k = kk * 8;
            const float* ab = sx + (m0 + gp) * SXS + k + tg;
            uint32_t a0 = __float_as_uint(ab[0]);
            uint32_t a1 = __float_as_uint(ab[8 * SXS]);
            uint32_t a2 = __float_as_uint(ab[4]);
            uint32_t a3 = __float_as_uint(ab[8 * SXS + 4]);
#pragma unroll
            for (int t = 0; t < 8; ++t) {
                const float* bb = sw + (t * 8 + gp) * SXS + k + tg;
                mma_tf32(acc[t], a0, a1, a2, a3,
                         __float_as_uint(bb[0]), __float_as_uint(bb[4]));
            }
        }
        // epilogue: bias, q-scale, tf32 round, head-major scatter
#pragma unroll
        for (int t = 0; t < 8; ++t) {
#pragma unroll
            for (int cc = 0; cc < 2; ++cc) {
                int col = c0 + t * 8 + 2 * tg + cc;
                int s = col / CDIM, rem = col % CDIM;
                int h = rem / HD, d = rem & (HD - 1);
                float bb = bias[col];
                float mul = (s == 0) ? SCALE : 1.f;
                float* dst = (s == 0) ? g_q : (s == 1) ? g_k : g_v;
                float* base = dst + (long)(bw * NH + h) * NTOK * HD + d;
                base[(m0 + gp) * HD]     = f2tff((acc[t][cc]     + bb) * mul);
                base[(m0 + gp + 8) * HD] = f2tff((acc[t][2 + cc] + bb) * mul);
            }
        }
    }
}

// ---------------- kernel 2: fused attention per (b,w,h) (tf32 MMA) ----------------
__global__ __launch_bounds__(288, 1) void attn_kernel(const float* __restrict__ mask) {
    extern __shared__ float sm[];
    float* sq = sm;                      // 144 x QVS
    float* sk = sq + NTOK * QVS;
    float* sv = sk + NTOK * QVS;
    float* sa = sv + NTOK * QVS;         // 144 x SAS
    int h  = blockIdx.x;
    int bw = blockIdx.y;
    int w  = bw % NW;
    int tid = threadIdx.x;
    int warp = tid >> 5, lane = tid & 31, gp = lane >> 2, tg = lane & 3;
    int m0 = warp * 16;

    long base = (long)(bw * NH + h) * NTOK * HD;
    const float* qp = g_q + base;
    const float* kp = g_k + base;
    const float* vp = g_v + base;
    for (int i = tid; i < NTOK * HD / 4; i += 288) {
        int n = i >> 3, d = (i & 7) * 4;
        *(float4*)(sq + n * QVS + d) = *(const float4*)(qp + n * HD + d);
        *(float4*)(sk + n * QVS + d) = *(const float4*)(kp + n * HD + d);
        *(float4*)(sv + n * QVS + d) = *(const float4*)(vp + n * HD + d);
    }
    __syncthreads();

    const float* bp = g_bias + (long)(w * NH + h) * NTOK * NTOK;
    const float* mp = mask + (long)bw * NTOK * NTOK;

    // QK^T: each warp m16 x 144, two passes of n=72
#pragma unroll
    for (int pass = 0; pass < 2; ++pass) {
        int nb = pass * 72;
        float acc[9][4];
#pragma unroll
        for (int t = 0; t < 9; t++)
#pragma unroll
            for (int j = 0; j < 4; j++) acc[t][j] = 0.f;
#pragma unroll
        for (int kk = 0; kk < 4; ++kk) {
            int k = kk * 8;
            const float* ab = sq + (m0 + gp) * QVS + k + tg;
            uint32_t a0 = __float_as_uint(ab[0]);
            uint32_t a1 = __float_as_uint(ab[8 * QVS]);
            uint32_t a2 = __float_as_uint(ab[4]);
            uint32_t a3 = __float_as_uint(ab[8 * QVS + 4]);
#pragma unroll
            for (int t = 0; t < 9; ++t) {
                const float* bb = sk + (nb + t * 8 + gp) * QVS + k + tg;
                mma_tf32(acc[t], a0, a1, a2, a3,
                         __float_as_uint(bb[0]), __float_as_uint(bb[4]));
            }
        }
#pragma unroll
        for (int t = 0; t < 9; ++t) {
            int mcol = nb + t * 8 + 2 * tg;
            int r0 = m0 + gp, r1 = r0 + 8;
            sa[r0 * SAS + mcol]     = acc[t][0] + bp[r0 * NTOK + mcol]     + mp[r0 * NTOK + mcol];
            sa[r0 * SAS + mcol + 1] = acc[t][1] + bp[r0 * NTOK + mcol + 1] + mp[r0 * NTOK + mcol + 1];
            sa[r1 * SAS + mcol]     = acc[t][2] + bp[r1 * NTOK + mcol]     + mp[r1 * NTOK + mcol];
            sa[r1 * SAS + mcol + 1] = acc[t][3] + bp[r1 * NTOK + mcol + 1] + mp[r1 * NTOK + mcol + 1];
        }
    }
    __syncthreads();

    // softmax: warp per row, 144 rows over 9 warps; normalized probs tf32-rounded
    for (int r = warp; r < NTOK; r += 9) {
        float mx = -1e30f;
        for (int c = lane; c < NTOK; c += 32) mx = fmaxf(mx, sa[r * SAS + c]);
#pragma unroll
        for (int o = 16; o; o >>= 1) mx = fmaxf(mx, __shfl_xor_sync(0xffffffffu, mx, o));
        float s = 0.f;
        for (int c = lane; c < NTOK; c += 32) {
            float e = __expf(sa[r * SAS + c] - mx);
            sa[r * SAS + c] = e;
            s += e;
        }
#pragma unroll
        for (int o = 16; o; o >>= 1) s += __shfl_xor_sync(0xffffffffu, s, o);
        float inv = 1.f / s;
        for (int c = lane; c < NTOK; c += 32) sa[r * SAS + c] = f2tff(sa[r * SAS + c] * inv);
    }
    __syncthreads();

    // P @ V: warp m16 x 32, K=144
    float acc2[4][4];
#pragma unroll
    for (int t = 0; t < 4; t++)
#pragma unroll
        for (int j = 0; j < 4; j++) acc2[t][j] = 0.f;
#pragma unroll
    for (int kk = 0; kk < 18; ++kk) {
        int k = kk * 8;
        const float* ab = sa + (m0 + gp) * SAS + k + tg;
        uint32_t a0 = __float_as_uint(ab[0]);
        uint32_t a1 = __float_as_uint(ab[8 * SAS]);
        uint32_t a2 = __float_as_uint(ab[4]);
        uint32_t a3 = __float_as_uint(ab[8 * SAS + 4]);
#pragma unroll
        for (int t = 0; t < 4; ++t) {
            const float* bb = sv + (k + tg) * QVS + t * 8 + gp;
            mma_tf32(acc2[t], a0, a1, a2, a3,
                     __float_as_uint(bb[0]), __float_as_uint(bb[4 * QVS]));
        }
    }
    float* op = g_o + (long)bw * NTOK * CDIM + h * HD;
#pragma unroll
    for (int t = 0; t < 4; ++t) {
        int d = t * 8 + 2 * tg;
        int r0 = m0 + gp, r1 = r0 + 8;
        op[r0 * CDIM + d]     = acc2[t][0];
        op[r0 * CDIM + d + 1] = acc2[t][1];
        op[r1 * CDIM + d]     = acc2[t][2];
        op[r1 * CDIM + d + 1] = acc2[t][3];
    }
}

// ---------------- kernel 3: output projection (tf32 MMA) ----------------
__global__ __launch_bounds__(288, 1) void proj_kernel(
    const float* __restrict__ wt, const float* __restrict__ bias,
    float* __restrict__ out) {
    extern __shared__ float sm[];
    float* sx = sm;                 // 144 x SXS
    float* sw = sm + NTOK * SXS;    // 64 x SXS
    int bw = blockIdx.x;
    int tid = threadIdx.x;
    int warp = tid >> 5, lane = tid & 31, gp = lane >> 2, tg = lane & 3;
    int m0 = warp * 16;

    const float* xp = g_o + (long)bw * NTOK * CDIM;
    for (int i = tid; i < NTOK * CDIM / 4; i += 288) {
        int e = i * 4;
        int n = e / CDIM, k = e % CDIM;
        float4 v = *(const float4*)(xp + e);
        float* d = sx + n * SXS + k;
        d[0] = f2tff(v.x); d[1] = f2tff(v.y); d[2] = f2tff(v.z); d[3] = f2tff(v.w);
    }

    for (int ct = 0; ct < 3; ++ct) {
        __syncthreads();
        int c0 = ct * 64;
        for (int i = tid; i < 64 * CDIM / 4; i += 288) {
            int e = i * 4;
            int j = e / CDIM, k = e % CDIM;
            float4 v = *(const float4*)(wt + (long)(c0 + j) * CDIM + k);
            float* d = sw + j * SXS + k;
            d[0] = f2tff(v.x); d[1] = f2tff(v.y); d[2] = f2tff(v.z); d[3] = f2tff(v.w);
        }
        __syncthreads();
        float acc[8][4];
#pragma unroll
        for (int t = 0; t < 8; t++)
#pragma unroll
            for (int j = 0; j < 4; j++) acc[t][j] = 0.f;
#pragma unroll
        for (int kk = 0; kk < 24; ++kk) {
            int k = kk * 8;
            const float* ab = sx + (m0 + gp) * SXS + k + tg;
            uint32_t a0 = __float_as_uint(ab[0]);
            uint32_t a1 = __float_as_uint(ab[8 * SXS]);
            uint32_t a2 = __float_as_uint(ab[4]);
            uint32_t a3 = __float_as_uint(ab[8 * SXS + 4]);
#pragma unroll
            for (int t = 0; t < 8; ++t) {
                const float* bb = sw + (t * 8 + gp) * SXS + k + tg;
                mma_tf32(acc[t], a0, a1, a2, a3,
                         __float_as_uint(bb[0]), __float_as_uint(bb[4]));
            }
        }
        float* ob = out + (long)bw * NTOK * CDIM;
#pragma unroll
        for (int t = 0; t < 8; ++t) {
#pragma unroll
            for (int cc = 0; cc < 2; ++cc) {
                int col = c0 + t * 8 + 2 * tg + cc;
                float bb = bias[col];
                ob[(m0 + gp) * CDIM + col]     = acc[t][cc]     + bb;
                ob[(m0 + gp + 8) * CDIM + col] = acc[t][2 + cc] + bb;
            }
        }
    }
}

// ---------------- launch ----------------
extern "C" void kernel_launch(void* const* d_in, const int* in_sizes, int n_in,
                              void* d_out, int out_size) {
    const float* x      = (const float*)d_in[0];
    const float* mask   = (const float*)d_in[1];
    const float* qkv_w  = (const float*)d_in[2];
    const float* qkv_b  = (const float*)d_in[3];
    const float* proj_w = (const float*)d_in[4];
    const float* proj_b = (const float*)d_in[5];
    const float* table  = (const float*)d_in[6];
    const int*   pos    = (const int*)d_in[7];
    float* out = (float*)d_out;

    const int lin_smem  = (NTOK * SXS + 64 * SXS) * 4;               // 163072 B
    const int attn_smem = (3 * NTOK * QVS + NTOK * SAS) * 4;         // 154368 B
    cudaFuncSetAttribute(qkv_kernel,  cudaFuncAttributeMaxDynamicSharedMemorySize, lin_smem);
    cudaFuncSetAttribute(proj_kernel, cudaFuncAttributeMaxDynamicSharedMemorySize, lin_smem);
    cudaFuncSetAttribute(attn_kernel, cudaFuncAttributeMaxDynamicSharedMemorySize, attn_smem);

    bias_pre_kernel<<<(NTOK * NTOK) / 32, 256>>>(table, pos);
    qkv_kernel<<<NBW, 288, lin_smem>>>(x, qkv_w, qkv_b);
    attn_kernel<<<dim3(NH, NBW), 288, attn_smem>>>(mask);
    proj_kernel<<<NBW, 288, lin_smem>>>(proj_w, proj_b, out);
}